// round 4
// baseline (speedup 1.0000x reference)
#include <cuda_runtime.h>
#include <cstdint>

// GNN layer: out = MLP_n([nf | segsum(MLP_e([nf[s]|nf[d]|ef]))])
//   A|B = nf @ [We1_rows0:128 | We1_rows128:256]   (per node)
//   C   = ef @ We1_rows256:320                     (per edge)
//   edge (mma.sync tf32): h = rna(leaky(A[s]+B[d]+C[e])); msg = h @ We2; RED into red[dst]
//   hn  = leaky([nf|red] @ Wn1); out = hn @ Wn2

constexpr int NN_MAX = 100000;
constexpr int NE_MAX = 500000;
constexpr float NEG = 0.01f;

__device__ __align__(128) float g_AB[(size_t)NN_MAX * 512];
__device__ __align__(128) float g_C[(size_t)NE_MAX * 256];
__device__ __align__(128) float g_red[(size_t)NN_MAX * 128];
__device__ __align__(128) float g_hn[(size_t)NN_MAX * 256];

__device__ __forceinline__ float lky(float x) { return x >= 0.0f ? x : NEG * x; }

__device__ __forceinline__ float rna_tf32(float x) {
    float r; asm("cvt.rna.tf32.f32 %0, %1;" : "=f"(r) : "f"(x)); return r;
}

__device__ __forceinline__ void red_add_v2(float* addr, float a, float b) {
    asm volatile("red.global.add.v2.f32 [%0], {%1,%2};" :: "l"(addr), "f"(a), "f"(b) : "memory");
}

__global__ void zero_kernel(float4* __restrict__ p, int n4) {
    int i = blockIdx.x * blockDim.x + threadIdx.x;
    if (i < n4) p[i] = make_float4(0.f, 0.f, 0.f, 0.f);
}

// Generic tiled FFMA GEMM: out[row,0:N] = act(X[row,0:K] @ W[K,N])
template <int K, int N, bool CONCAT, bool LEAKY>
__global__ void gemm_k(const float* __restrict__ X1, const float* __restrict__ X2,
                       const float* __restrict__ W, float* __restrict__ out,
                       int M, int out_stride) {
    constexpr int CT = N / 4;
    constexpr int RG = 256 / CT;
    constexpr int TR = RG * 8;
    constexpr int K4 = K / 4;
    extern __shared__ float xs[];

    const int tid = threadIdx.x;
    const int row0 = blockIdx.x * TR;

    for (int idx = tid; idx < TR * K4; idx += 256) {
        int r = idx / K4, k4 = idx % K4;
        int row = row0 + r;
        float4 v = make_float4(0.f, 0.f, 0.f, 0.f);
        if (row < M) {
            if (CONCAT) {
                v = (k4 < 32) ? ((const float4*)X1)[(long)row * 32 + k4]
                              : ((const float4*)X2)[(long)row * 32 + (k4 - 32)];
            } else {
                v = ((const float4*)X1)[(long)row * K4 + k4];
            }
        }
        *(float4*)&xs[r * K + k4 * 4] = v;
    }
    __syncthreads();

    const int tx = tid % CT, ty = tid / CT;
    const int c = tx * 4;

    float4 acc[8];
#pragma unroll
    for (int i = 0; i < 8; i++) acc[i] = make_float4(0.f, 0.f, 0.f, 0.f);

    for (int k = 0; k < K; k += 4) {
        float4 w0 = __ldg((const float4*)&W[(k + 0) * N + c]);
        float4 w1 = __ldg((const float4*)&W[(k + 1) * N + c]);
        float4 w2 = __ldg((const float4*)&W[(k + 2) * N + c]);
        float4 w3 = __ldg((const float4*)&W[(k + 3) * N + c]);
#pragma unroll
        for (int i = 0; i < 8; i++) {
            float4 h = *(const float4*)&xs[(ty * 8 + i) * K + k];
            acc[i].x = fmaf(h.x, w0.x, fmaf(h.y, w1.x, fmaf(h.z, w2.x, fmaf(h.w, w3.x, acc[i].x))));
            acc[i].y = fmaf(h.x, w0.y, fmaf(h.y, w1.y, fmaf(h.z, w2.y, fmaf(h.w, w3.y, acc[i].y))));
            acc[i].z = fmaf(h.x, w0.z, fmaf(h.y, w1.z, fmaf(h.z, w2.z, fmaf(h.w, w3.z, acc[i].z))));
            acc[i].w = fmaf(h.x, w0.w, fmaf(h.y, w1.w, fmaf(h.z, w2.w, fmaf(h.w, w3.w, acc[i].w))));
        }
    }

#pragma unroll
    for (int i = 0; i < 8; i++) {
        int row = row0 + ty * 8 + i;
        if (row < M) {
            float4 v = acc[i];
            if (LEAKY) { v.x = lky(v.x); v.y = lky(v.y); v.z = lky(v.z); v.w = lky(v.w); }
            *(float4*)&out[(long)row * out_stride + c] = v;
        }
    }
}

// ---------------- tf32 mma.sync edge kernel ----------------
// Persistent CTAs, 512 threads (16 warps). Tile = 64 edges -> 128 edge-dir rows.
// h[128][256] gathered (K in 2 halves of 128 into smem), msg[128][128] = h @ We2
// via mma.sync.m16n8k8 tf32, scattered into red[dst] with red.global.add.v2.
//
// k-permutation trick: within each hw k-tile of 8, hw lanes k={c, c+4} carry
// actual k={2c, 2c+1}, applied identically to A and B, so both fragments are
// single 8-byte vector loads from shared memory.

constexpr int HS_STRIDE  = 132;   // 128 + 4 pad (floats)
constexpr int W2T_STRIDE = 264;   // 256 + 8 pad (floats)
constexpr int SM_W2T = 0;                        // 128 * 264 * 4 = 135168 B
constexpr int SM_HS  = 135168;                   // 128 * 132 * 4 = 67584 B
constexpr int SM_IDX = 202752;                   // se[64], sd[64], dd[128]
constexpr int SM_EDGE_TOTAL = 202752 + 256 * 4;  // 203776 B

__global__ void __launch_bounds__(512, 1)
edge_mma_kernel(const float* __restrict__ AB, const float* __restrict__ Cg,
                const float* __restrict__ W2,
                const int* __restrict__ src, const int* __restrict__ dst,
                float* __restrict__ red, int E, int ntiles) {
    extern __shared__ char smem[];
    float* w2t = (float*)(smem + SM_W2T);
    float* hs  = (float*)(smem + SM_HS);
    int* se = (int*)(smem + SM_IDX);
    int* sd = se + 64;
    int* dd = se + 128;

    const int tid = threadIdx.x;

    // One-time: We2 (256x128 row-major) -> We2^T n-major, rna-rounded.
    for (int idx = tid; idx < 256 * 128; idx += 512) {
        int k = idx >> 7, n = idx & 127;
        w2t[n * W2T_STRIDE + k] = rna_tf32(W2[idx]);
    }

    // roles
    const int gr = tid >> 2;          // gather row 0..127
    const int gq = tid & 3;           // quarter of 128 floats
    const int w = tid >> 5, lane = tid & 31;
    const int fg = lane >> 2, fc = lane & 3;      // fragment group / thread-in-group
    const int r0 = (w & 7) * 16;                  // warp's row base
    const int cb = (w >> 3) * 64;                 // warp's col base

    for (int t = blockIdx.x; t < ntiles; t += gridDim.x) {
        __syncthreads();   // covers w2t init (first iter) + prev-iter epilogue/hs reads
        if (tid < 64) {
            long e = (long)t * 64 + tid;
            int sv = -1, dv = -1;
            if (e < (long)E) { sv = src[e]; dv = dst[e]; }
            se[tid] = sv; sd[tid] = dv;
        }
        __syncthreads();

        const int er = gr >> 1;
        const bool rev = gr & 1;
        const int sv = se[er], dv = sd[er];
        const bool valid = (sv >= 0);
        const int s = rev ? dv : sv;
        const int d = rev ? sv : dv;
        if (gq == 0) dd[gr] = valid ? d : -1;
        const long eIdx = (long)t * 64 + er;

        float d0[8], d1[8], d2[8], d3[8];
#pragma unroll
        for (int nt = 0; nt < 8; nt++) { d0[nt] = d1[nt] = d2[nt] = d3[nt] = 0.f; }

#pragma unroll
        for (int kh = 0; kh < 2; kh++) {
            // ---- gather + add + leaky + rna -> hs (this thread's 32 floats) ----
            {
                const int kbase = kh * 128 + gq * 32;
                const float4* pa = (const float4*)(AB + (size_t)(valid ? s : 0) * 512 + kbase);
                const float4* pb = (const float4*)(AB + (size_t)(valid ? d : 0) * 512 + 256 + kbase);
                const float4* pc = (const float4*)(Cg + (size_t)(valid ? eIdx : 0) * 256 + kbase);
                float* hrow = &hs[gr * HS_STRIDE + gq * 32];
#pragma unroll
                for (int j = 0; j < 8; j++) {
                    float4 hv = make_float4(0.f, 0.f, 0.f, 0.f);
                    if (valid) {
                        float4 a = pa[j], b = pb[j], c = pc[j];
                        hv.x = rna_tf32(lky(a.x + b.x + c.x));
                        hv.y = rna_tf32(lky(a.y + b.y + c.y));
                        hv.z = rna_tf32(lky(a.z + b.z + c.z));
                        hv.w = rna_tf32(lky(a.w + b.w + c.w));
                    }
                    *(float4*)&hrow[j * 4] = hv;
                }
            }
            __syncthreads();

            // ---- mma: 16 k-tiles x 8 n-tiles ----
            {
                const uint32_t* hA  = (const uint32_t*)&hs[(r0 + fg) * HS_STRIDE + 2 * fc];
                const uint32_t* hA8 = (const uint32_t*)&hs[(r0 + fg + 8) * HS_STRIDE + 2 * fc];
                const int wkb = kh * 128 + 2 * fc;
#pragma unroll
                for (int kt = 0; kt < 16; kt++) {
                    uint2 av  = *(const uint2*)&hA[kt * 8];
                    uint2 av8 = *(const uint2*)&hA8[kt * 8];
#pragma unroll
                    for (int nt = 0; nt < 8; nt++) {
                        uint2 bv = *(const uint2*)&w2t[(size_t)(cb + nt * 8 + fg) * W2T_STRIDE + wkb + kt * 8];
                        asm volatile(
                            "mma.sync.aligned.m16n8k8.row.col.f32.tf32.tf32.f32 "
                            "{%0,%1,%2,%3}, {%4,%5,%6,%7}, {%8,%9}, {%0,%1,%2,%3};"
                            : "+f"(d0[nt]), "+f"(d1[nt]), "+f"(d2[nt]), "+f"(d3[nt])
                            : "r"(av.x), "r"(av8.x), "r"(av.y), "r"(av8.y),
                              "r"(bv.x), "r"(bv.y));
                    }
                }
            }
            __syncthreads();
        }

        // ---- epilogue: scatter D into red[dst] ----
        {
            const int dA = dd[r0 + fg];
            const int dB = dd[r0 + fg + 8];
#pragma unroll
            for (int nt = 0; nt < 8; nt++) {
                int col = cb + nt * 8 + 2 * fc;
                if (dA >= 0) red_add_v2(&red[(size_t)dA * 128 + col], d0[nt], d1[nt]);
                if (dB >= 0) red_add_v2(&red[(size_t)dB * 128 + col], d2[nt], d3[nt]);
            }
        }
    }
}

extern "C" void kernel_launch(void* const* d_in, const int* in_sizes, int n_in,
                              void* d_out, int out_size) {
    const float* nf  = (const float*)d_in[0];
    const float* ef  = (const float*)d_in[1];
    const int*   src = (const int*)d_in[2];
    const int*   dst = (const int*)d_in[3];
    const float* We1 = (const float*)d_in[4];   // (320, 256)
    const float* We2 = (const float*)d_in[5];   // (256, 128)
    const float* Wn1 = (const float*)d_in[6];   // (256, 256)
    const float* Wn2 = (const float*)d_in[7];   // (256, 128)

    const int N = in_sizes[0] / 128;
    const int E = in_sizes[2];

    float *AB, *C, *red, *hn;
    cudaGetSymbolAddress((void**)&AB, g_AB);
    cudaGetSymbolAddress((void**)&C, g_C);
    cudaGetSymbolAddress((void**)&red, g_red);
    cudaGetSymbolAddress((void**)&hn, g_hn);

    cudaFuncSetAttribute((const void*)edge_mma_kernel,
                         cudaFuncAttributeMaxDynamicSharedMemorySize, SM_EDGE_TOTAL);
    cudaFuncSetAttribute((const void*)gemm_k<256, 128, false, false>,
                         cudaFuncAttributeMaxDynamicSharedMemorySize, 64 * 256 * 4);

    int smc = 0;
    cudaDeviceGetAttribute(&smc, cudaDevAttrMultiProcessorCount, 0);
    if (smc <= 0) smc = 148;

    // 0) zero segment-sum accumulator
    int n4 = N * 128 / 4;
    zero_kernel<<<(n4 + 255) / 256, 256>>>((float4*)red, n4);

    // 1) A = nf @ We1[0:128,:]   -> g_AB cols [0,256), row stride 512
    gemm_k<128, 256, false, false><<<(N + 31) / 32, 256, 32 * 128 * 4>>>(
        nf, nullptr, We1, AB, N, 512);
    // 2) B = nf @ We1[128:256,:] -> g_AB cols [256,512)
    gemm_k<128, 256, false, false><<<(N + 31) / 32, 256, 32 * 128 * 4>>>(
        nf, nullptr, We1 + 128 * 256, AB + 256, N, 512);
    // 3) C = ef @ We1[256:320,:]
    gemm_k<64, 256, false, false><<<(E + 31) / 32, 256, 32 * 64 * 4>>>(
        ef, nullptr, We1 + 256 * 256, C, E, 256);
    // 4) edge messages on tensor cores (mma.sync tf32) + scatter-add (persistent)
    int ntiles = (E + 63) / 64;
    int grid = smc < ntiles ? smc : ntiles;
    edge_mma_kernel<<<grid, 512, SM_EDGE_TOTAL>>>(AB, C, We2, src, dst, red, E, ntiles);
    // 5) hn = leaky([nf | red] @ Wn1)
    gemm_k<256, 256, true, true><<<(N + 31) / 32, 256, 32 * 256 * 4>>>(
        nf, red, Wn1, hn, N, 256);
    // 6) out = hn @ Wn2
    gemm_k<256, 128, false, false><<<(N + 63) / 64, 256, 64 * 256 * 4>>>(
        hn, nullptr, Wn2, (float*)d_out, N, 128);
}

// round 5
// speedup vs baseline: 1.3925x; 1.3925x over previous
#include <cuda_runtime.h>
#include <cstdint>

// GNN layer, all GEMMs on tf32 mma.sync (validated fragment math from R3):
//   A|B = nf @ [We1_rows0:128 | We1_rows128:256]   (per node)
//   C   = ef @ We1_rows256:320                     (per edge)
//   edge: h = rna(leaky(A[s]+B[d]+C[e])); msg = h @ We2; RED into red[dst]
//   hn  = leaky([nf|red] @ Wn1); out = hn @ Wn2
// Weights live in global memory pre-shuffled into per-mma fragment order:
//   Wf[((ntg*(K/8)+kt)*64 + lane*2 + j)] = rna(W[(kt*8 + 2*(lane&3) + j)*N + ntg*8 + (lane>>2)])
// so every B-fragment load is one coalesced LDG.64 (k-permutation applied to A and B alike).

constexpr int NN_MAX = 100000;
constexpr int NE_MAX = 500000;
constexpr float NEG = 0.01f;

__device__ __align__(128) float g_AB[(size_t)NN_MAX * 512];
__device__ __align__(128) float g_C[(size_t)NE_MAX * 256];
__device__ __align__(128) float g_red[(size_t)NN_MAX * 128];
__device__ __align__(128) float g_hn[(size_t)NN_MAX * 256];
// weight fragment buffers
__device__ __align__(128) float g_fA[128 * 256];
__device__ __align__(128) float g_fB[128 * 256];
__device__ __align__(128) float g_fC[64 * 256];
__device__ __align__(128) float g_fN1[256 * 256];
__device__ __align__(128) float g_fN2[256 * 128];
__device__ __align__(128) float g_fE2[256 * 128];

__device__ __forceinline__ float lky(float x) { return x >= 0.0f ? x : NEG * x; }

__device__ __forceinline__ float rna_tf32(float x) {
    float r; asm("cvt.rna.tf32.f32 %0, %1;" : "=f"(r) : "f"(x)); return r;
}

__device__ __forceinline__ void red_add_v2(float* addr, float a, float b) {
    asm volatile("red.global.add.v2.f32 [%0], {%1,%2};" :: "l"(addr), "f"(a), "f"(b) : "memory");
}

#define MMA_TF32(D0, D1, D2, D3, AV, AV8, BV)                                   \
    asm volatile("mma.sync.aligned.m16n8k8.row.col.f32.tf32.tf32.f32 "          \
                 "{%0,%1,%2,%3}, {%4,%5,%6,%7}, {%8,%9}, {%0,%1,%2,%3};"        \
                 : "+f"(D0), "+f"(D1), "+f"(D2), "+f"(D3)                       \
                 : "r"((AV).x), "r"((AV8).x), "r"((AV).y), "r"((AV8).y),        \
                   "r"((BV).x), "r"((BV).y))

__global__ void zero_kernel(float4* __restrict__ p, int n4) {
    int i = blockIdx.x * blockDim.x + threadIdx.x;
    if (i < n4) p[i] = make_float4(0.f, 0.f, 0.f, 0.f);
}

// ---- weight -> fragment-order shuffle (one-time, tiny) ----
template <int K, int N>
__global__ void setup_frag(const float* __restrict__ W, float* __restrict__ Wf) {
    int fi = blockIdx.x * 256 + threadIdx.x;
    if (fi >= K * N) return;
    int j = fi & 1;
    int lane = (fi >> 1) & 31;
    int kt = (fi >> 6) % (K / 8);
    int ntg = fi / (64 * (K / 8));
    int fc = lane & 3, fg = lane >> 2;
    int k = kt * 8 + 2 * fc + j;
    int n = ntg * 8 + fg;
    Wf[fi] = rna_tf32(W[k * N + n]);
}

// ---- generic tf32 mma GEMM: out[row,0:N] = act(X[row,0:K] @ W) ----
// 256 threads, tile M=64. Warp grid 2(M) x 4(N): Mw=32, Nw=N/4.
template <int K, int N, bool CONCAT, bool LEAKY>
__global__ void __launch_bounds__(256, 2)
mma_gemm(const float* __restrict__ X1, const float* __restrict__ X2,
         const float* __restrict__ Wf, float* __restrict__ out,
         int M, int ostride) {
    constexpr int ST = K + 8;      // (K+8) % 32 == 8 -> conflict-free A-frag LDS
    constexpr int KT = K / 8;
    constexpr int NT = N / 32;     // ntiles per warp (Nw = N/4 = NT*8)
    constexpr int K4 = K / 4;
    extern __shared__ float xs[];  // 64 * ST floats

    const int tid = threadIdx.x;
    const int row0 = blockIdx.x * 64;

    for (int idx = tid; idx < 64 * K4; idx += 256) {
        int r = idx / K4, k4 = idx % K4;
        int row = row0 + r;
        float4 v = make_float4(0.f, 0.f, 0.f, 0.f);
        if (row < M) {
            if (CONCAT)
                v = (k4 < 32) ? ((const float4*)X1)[(size_t)row * 32 + k4]
                              : ((const float4*)X2)[(size_t)row * 32 + (k4 - 32)];
            else
                v = ((const float4*)X1)[(size_t)row * K4 + k4];
        }
        v.x = rna_tf32(v.x); v.y = rna_tf32(v.y);
        v.z = rna_tf32(v.z); v.w = rna_tf32(v.w);
        *(float4*)&xs[r * ST + k4 * 4] = v;
    }
    __syncthreads();

    const int w = tid >> 5, lane = tid & 31;
    const int fg = lane >> 2, fc = lane & 3;
    const int r0 = (w & 1) * 32;
    const int wc = w >> 1;                 // 0..3

    float d0[2][NT], d1[2][NT], d2[2][NT], d3[2][NT];
#pragma unroll
    for (int mt = 0; mt < 2; mt++)
#pragma unroll
        for (int nt = 0; nt < NT; nt++) { d0[mt][nt] = d1[mt][nt] = d2[mt][nt] = d3[mt][nt] = 0.f; }

    for (int kt = 0; kt < KT; kt++) {
        uint2 a0  = *(const uint2*)&xs[(r0 + fg)      * ST + kt * 8 + 2 * fc];
        uint2 a08 = *(const uint2*)&xs[(r0 + fg + 8)  * ST + kt * 8 + 2 * fc];
        uint2 a1  = *(const uint2*)&xs[(r0 + fg + 16) * ST + kt * 8 + 2 * fc];
        uint2 a18 = *(const uint2*)&xs[(r0 + fg + 24) * ST + kt * 8 + 2 * fc];
#pragma unroll
        for (int nt = 0; nt < NT; nt++) {
            uint2 bv = __ldg((const uint2*)&Wf[(size_t)((wc * NT + nt) * KT + kt) * 64 + lane * 2]);
            MMA_TF32(d0[0][nt], d1[0][nt], d2[0][nt], d3[0][nt], a0, a08, bv);
            MMA_TF32(d0[1][nt], d1[1][nt], d2[1][nt], d3[1][nt], a1, a18, bv);
        }
    }

#pragma unroll
    for (int mt = 0; mt < 2; mt++) {
#pragma unroll
        for (int nt = 0; nt < NT; nt++) {
            int row = row0 + r0 + mt * 16 + fg;
            int col = wc * (NT * 8) + nt * 8 + 2 * fc;
            float v0 = d0[mt][nt], v1 = d1[mt][nt], v2 = d2[mt][nt], v3 = d3[mt][nt];
            if (LEAKY) { v0 = lky(v0); v1 = lky(v1); v2 = lky(v2); v3 = lky(v3); }
            if (row < M)     *(float2*)&out[(size_t)row * ostride + col]       = make_float2(v0, v1);
            if (row + 8 < M) *(float2*)&out[(size_t)(row + 8) * ostride + col] = make_float2(v2, v3);
        }
    }
}

// ---- edge kernel: tile = 32 edges -> 64 edge-dir rows; K=256, N=128 ----
// gather h into smem -> mma (B frags coalesced from g_fE2 via L1) -> red-scatter.
constexpr int EST = 264;           // 256 + 8
constexpr int SM_EDGE = 64 * EST * 4;

__global__ void __launch_bounds__(256, 3)
edge_mma2(const float* __restrict__ AB, const float* __restrict__ Cg,
          const float* __restrict__ Wf,
          const int* __restrict__ src, const int* __restrict__ dst,
          float* __restrict__ red, int E) {
    extern __shared__ float hs[];  // 64 * 264
    __shared__ int se[32], sd[32], dd[64];

    const int tid = threadIdx.x;
    const int t = blockIdx.x;

    if (tid < 32) {
        int e = t * 32 + tid;
        int sv = -1, dv = -1;
        if (e < E) { sv = src[e]; dv = dst[e]; }
        se[tid] = sv; sd[tid] = dv;
    }
    __syncthreads();

    // ---- gather + add + leaky + rna -> hs ----
    {
        const int gr = tid >> 2, gq = tid & 3;      // row 0..63, quarter (64 floats)
        const int er = gr >> 1;
        const bool rev = gr & 1;
        const int sv = se[er], dv = sd[er];
        const bool valid = (sv >= 0);
        const int s = rev ? dv : sv;
        const int d = rev ? sv : dv;
        if (gq == 0) dd[gr] = valid ? d : -1;
        const int e = t * 32 + er;

        const float4* pa = (const float4*)(AB + (size_t)(valid ? s : 0) * 512) + gq * 16;
        const float4* pb = (const float4*)(AB + (size_t)(valid ? d : 0) * 512 + 256) + gq * 16;
        const float4* pc = (const float4*)(Cg + (size_t)(valid ? e : 0) * 256) + gq * 16;
        float* hrow = &hs[gr * EST + gq * 64];
#pragma unroll
        for (int j = 0; j < 8; j++) {
            float4 h0 = make_float4(0.f, 0.f, 0.f, 0.f);
            float4 h1 = h0;
            if (valid) {
                float4 a0 = pa[2 * j], a1 = pa[2 * j + 1];
                float4 b0 = pb[2 * j], b1 = pb[2 * j + 1];
                float4 c0 = pc[2 * j], c1 = pc[2 * j + 1];
                h0.x = rna_tf32(lky(a0.x + b0.x + c0.x));
                h0.y = rna_tf32(lky(a0.y + b0.y + c0.y));
                h0.z = rna_tf32(lky(a0.z + b0.z + c0.z));
                h0.w = rna_tf32(lky(a0.w + b0.w + c0.w));
                h1.x = rna_tf32(lky(a1.x + b1.x + c1.x));
                h1.y = rna_tf32(lky(a1.y + b1.y + c1.y));
                h1.z = rna_tf32(lky(a1.z + b1.z + c1.z));
                h1.w = rna_tf32(lky(a1.w + b1.w + c1.w));
            }
            *(float4*)&hrow[j * 8] = h0;
            *(float4*)&hrow[j * 8 + 4] = h1;
        }
    }
    __syncthreads();

    // ---- mma: warp grid 2(M) x 4(N); Mw=32, Nw=32; K=256 (32 kt) ----
    const int w = tid >> 5, lane = tid & 31;
    const int fg = lane >> 2, fc = lane & 3;
    const int r0 = (w & 1) * 32;
    const int wc = w >> 1;

    float d0[2][4], d1[2][4], d2[2][4], d3[2][4];
#pragma unroll
    for (int mt = 0; mt < 2; mt++)
#pragma unroll
        for (int nt = 0; nt < 4; nt++) { d0[mt][nt] = d1[mt][nt] = d2[mt][nt] = d3[mt][nt] = 0.f; }

    for (int kt = 0; kt < 32; kt++) {
        uint2 a0  = *(const uint2*)&hs[(r0 + fg)      * EST + kt * 8 + 2 * fc];
        uint2 a08 = *(const uint2*)&hs[(r0 + fg + 8)  * EST + kt * 8 + 2 * fc];
        uint2 a1  = *(const uint2*)&hs[(r0 + fg + 16) * EST + kt * 8 + 2 * fc];
        uint2 a18 = *(const uint2*)&hs[(r0 + fg + 24) * EST + kt * 8 + 2 * fc];
#pragma unroll
        for (int nt = 0; nt < 4; nt++) {
            uint2 bv = __ldg((const uint2*)&Wf[(size_t)((wc * 4 + nt) * 32 + kt) * 64 + lane * 2]);
            MMA_TF32(d0[0][nt], d1[0][nt], d2[0][nt], d3[0][nt], a0, a08, bv);
            MMA_TF32(d0[1][nt], d1[1][nt], d2[1][nt], d3[1][nt], a1, a18, bv);
        }
    }

    // ---- scatter-add into red[dst] ----
#pragma unroll
    for (int mt = 0; mt < 2; mt++) {
        const int rA = r0 + mt * 16 + fg;
        const int dA = dd[rA];
        const int dB = dd[rA + 8];
#pragma unroll
        for (int nt = 0; nt < 4; nt++) {
            int col = wc * 32 + nt * 8 + 2 * fc;
            if (dA >= 0) red_add_v2(&red[(size_t)dA * 128 + col], d0[mt][nt], d1[mt][nt]);
            if (dB >= 0) red_add_v2(&red[(size_t)dB * 128 + col], d2[mt][nt], d3[mt][nt]);
        }
    }
}

extern "C" void kernel_launch(void* const* d_in, const int* in_sizes, int n_in,
                              void* d_out, int out_size) {
    const float* nf  = (const float*)d_in[0];
    const float* ef  = (const float*)d_in[1];
    const int*   src = (const int*)d_in[2];
    const int*   dst = (const int*)d_in[3];
    const float* We1 = (const float*)d_in[4];   // (320, 256)
    const float* We2 = (const float*)d_in[5];   // (256, 128)
    const float* Wn1 = (const float*)d_in[6];   // (256, 256)
    const float* Wn2 = (const float*)d_in[7];   // (256, 128)

    const int N = in_sizes[0] / 128;
    const int E = in_sizes[2];

    float *AB, *C, *red, *hn, *fA, *fB, *fC, *fN1, *fN2, *fE2;
    cudaGetSymbolAddress((void**)&AB, g_AB);
    cudaGetSymbolAddress((void**)&C, g_C);
    cudaGetSymbolAddress((void**)&red, g_red);
    cudaGetSymbolAddress((void**)&hn, g_hn);
    cudaGetSymbolAddress((void**)&fA, g_fA);
    cudaGetSymbolAddress((void**)&fB, g_fB);
    cudaGetSymbolAddress((void**)&fC, g_fC);
    cudaGetSymbolAddress((void**)&fN1, g_fN1);
    cudaGetSymbolAddress((void**)&fN2, g_fN2);
    cudaGetSymbolAddress((void**)&fE2, g_fE2);

    cudaFuncSetAttribute((const void*)edge_mma2,
                         cudaFuncAttributeMaxDynamicSharedMemorySize, SM_EDGE);
    cudaFuncSetAttribute((const void*)mma_gemm<256, 256, true, true>,
                         cudaFuncAttributeMaxDynamicSharedMemorySize, 64 * 264 * 4);
    cudaFuncSetAttribute((const void*)mma_gemm<256, 128, false, false>,
                         cudaFuncAttributeMaxDynamicSharedMemorySize, 64 * 264 * 4);

    // ---- one-time weight shuffles (tiny) ----
    setup_frag<128, 256><<<(128 * 256 + 255) / 256, 256>>>(We1, fA);
    setup_frag<128, 256><<<(128 * 256 + 255) / 256, 256>>>(We1 + 128 * 256, fB);
    setup_frag<64, 256><<<(64 * 256 + 255) / 256, 256>>>(We1 + 256 * 256, fC);
    setup_frag<256, 256><<<(256 * 256 + 255) / 256, 256>>>(Wn1, fN1);
    setup_frag<256, 128><<<(256 * 128 + 255) / 256, 256>>>(Wn2, fN2);
    setup_frag<256, 128><<<(256 * 128 + 255) / 256, 256>>>(We2, fE2);

    // 0) zero segment-sum accumulator
    int n4 = N * 128 / 4;
    zero_kernel<<<(n4 + 255) / 256, 256>>>((float4*)red, n4);

    // 1) A-half, 2) B-half: nf @ We1 halves -> g_AB (row stride 512)
    mma_gemm<128, 256, false, false><<<(N + 63) / 64, 256, 64 * 136 * 4>>>(
        nf, nullptr, fA, AB, N, 512);
    mma_gemm<128, 256, false, false><<<(N + 63) / 64, 256, 64 * 136 * 4>>>(
        nf, nullptr, fB, AB + 256, N, 512);
    // 3) C = ef @ We1_ef
    mma_gemm<64, 256, false, false><<<(E + 63) / 64, 256, 64 * 72 * 4>>>(
        ef, nullptr, fC, C, E, 256);
    // 4) edge messages + scatter-add
    int etiles = (2 * E + 63) / 64;
    edge_mma2<<<etiles, 256, SM_EDGE>>>(AB, C, fE2, src, dst, red, E);
    // 5) hn = leaky([nf | red] @ Wn1)
    mma_gemm<256, 256, true, true><<<(N + 63) / 64, 256, 64 * 264 * 4>>>(
        nf, red, fN1, hn, N, 256);
    // 6) out = hn @ Wn2
    mma_gemm<256, 128, false, false><<<(N + 63) / 64, 256, 64 * 264 * 4>>>(
        hn, nullptr, fN2, (float*)d_out, N, 128);
}

// round 6
// speedup vs baseline: 1.7740x; 1.2740x over previous
#include <cuda_runtime.h>
#include <cstdint>

// GNN layer, all GEMMs on tf32 mma.sync m16n8k8 (fragment math validated R3/R4):
//   A|B = nf @ [We1_rows0:128 | We1_rows128:256]   (per node, precomputed)
//   edge (fused): Cfrag = ef @ We1_ef (mma, from global ef);
//                 h = rna(leaky(Cfrag + A[s] + B[d])) -> smem;
//                 msg = h @ We2 (mma); red.global.add.v4 into red[dst]
//   node (fused): hn = leaky([nf|red] @ Wn1) -> smem; out = hn @ Wn2
// Weights pre-shuffled to per-mma fragment order (coalesced LDG.64 B-frags):
//   Wf[((ntg*(K/8)+kt)*64 + lane*2 + j)] = rna(W[(kt*8+2*(lane&3)+j)*N + ntg*8 + (lane>>2)])

constexpr int NN_MAX = 100000;
constexpr int NE_MAX = 500000;
constexpr float NEG = 0.01f;

__device__ __align__(128) float g_AB[(size_t)NN_MAX * 512];
__device__ __align__(128) float g_red[(size_t)NN_MAX * 128];
__device__ __align__(128) float g_fA[128 * 256];
__device__ __align__(128) float g_fB[128 * 256];
__device__ __align__(128) float g_fC[64 * 256];
__device__ __align__(128) float g_fN1[256 * 256];
__device__ __align__(128) float g_fN2[256 * 128];
__device__ __align__(128) float g_fE2[256 * 128];

__device__ __forceinline__ float lky(float x) { return x >= 0.0f ? x : NEG * x; }

__device__ __forceinline__ float rna_tf32(float x) {
    float r; asm("cvt.rna.tf32.f32 %0, %1;" : "=f"(r) : "f"(x)); return r;
}

__device__ __forceinline__ void red_add_v4(float* addr, float a, float b, float c, float d) {
    asm volatile("red.global.add.v4.f32 [%0], {%1,%2,%3,%4};"
                 :: "l"(addr), "f"(a), "f"(b), "f"(c), "f"(d) : "memory");
}

#define MMA_TF32(D0, D1, D2, D3, AV, AV8, BV)                                   \
    asm volatile("mma.sync.aligned.m16n8k8.row.col.f32.tf32.tf32.f32 "          \
                 "{%0,%1,%2,%3}, {%4,%5,%6,%7}, {%8,%9}, {%0,%1,%2,%3};"        \
                 : "+f"(D0), "+f"(D1), "+f"(D2), "+f"(D3)                       \
                 : "r"((AV).x), "r"((AV8).x), "r"((AV).y), "r"((AV8).y),        \
                   "r"((BV).x), "r"((BV).y))

__global__ void zero_kernel(float4* __restrict__ p, int n4) {
    int i = blockIdx.x * blockDim.x + threadIdx.x;
    if (i < n4) p[i] = make_float4(0.f, 0.f, 0.f, 0.f);
}

// ---- weight -> fragment-order shuffle (one-time, tiny) ----
template <int K, int N>
__global__ void setup_frag(const float* __restrict__ W, float* __restrict__ Wf) {
    int fi = blockIdx.x * 256 + threadIdx.x;
    if (fi >= K * N) return;
    int j = fi & 1;
    int lane = (fi >> 1) & 31;
    int kt = (fi >> 6) % (K / 8);
    int ntg = fi / (64 * (K / 8));
    int fc = lane & 3, fg = lane >> 2;
    int k = kt * 8 + 2 * fc + j;
    int n = ntg * 8 + fg;
    Wf[fi] = rna_tf32(W[k * N + n]);
}

// ---- generic tf32 mma GEMM, 1(M)x8(N) warp grid, tile M=64 ----
template <int K, int N>
__global__ void __launch_bounds__(256, 2)
mma_gemm(const float* __restrict__ X1, const float* __restrict__ Wf,
         float* __restrict__ out, int M, int ostride) {
    constexpr int ST = K + 8;
    constexpr int KT = K / 8;
    constexpr int NT = N / 64;         // ntiles per warp (warp covers N/8 cols)
    constexpr int K4 = K / 4;
    extern __shared__ float xs[];      // 64 * ST

    const int tid = threadIdx.x;
    const int row0 = blockIdx.x * 64;

    for (int idx = tid; idx < 64 * K4; idx += 256) {
        int r = idx / K4, k4 = idx % K4;
        int row = row0 + r;
        float4 v = make_float4(0.f, 0.f, 0.f, 0.f);
        if (row < M) v = ((const float4*)X1)[(size_t)row * K4 + k4];
        v.x = rna_tf32(v.x); v.y = rna_tf32(v.y);
        v.z = rna_tf32(v.z); v.w = rna_tf32(v.w);
        *(float4*)&xs[r * ST + k4 * 4] = v;
    }
    __syncthreads();

    const int w = tid >> 5, lane = tid & 31;
    const int fg = lane >> 2, fc = lane & 3;

    float d0[4][NT], d1[4][NT], d2[4][NT], d3[4][NT];
#pragma unroll
    for (int mt = 0; mt < 4; mt++)
#pragma unroll
        for (int nt = 0; nt < NT; nt++) { d0[mt][nt] = d1[mt][nt] = d2[mt][nt] = d3[mt][nt] = 0.f; }

    for (int kt = 0; kt < KT; kt++) {
        uint2 a[8];
#pragma unroll
        for (int j = 0; j < 8; j++)
            a[j] = *(const uint2*)&xs[(fg + j * 8) * ST + kt * 8 + 2 * fc];
#pragma unroll
        for (int nt = 0; nt < NT; nt++) {
            uint2 bv = __ldg((const uint2*)&Wf[(size_t)((w * NT + nt) * KT + kt) * 64 + lane * 2]);
#pragma unroll
            for (int mt = 0; mt < 4; mt++)
                MMA_TF32(d0[mt][nt], d1[mt][nt], d2[mt][nt], d3[mt][nt],
                         a[2 * mt], a[2 * mt + 1], bv);
        }
    }

#pragma unroll
    for (int mt = 0; mt < 4; mt++) {
#pragma unroll
        for (int nt = 0; nt < NT; nt++) {
            int row = row0 + mt * 16 + fg;
            int col = w * (NT * 8) + nt * 8 + 2 * fc;
            if (row < M)     *(float2*)&out[(size_t)row * ostride + col]       = make_float2(d0[mt][nt], d1[mt][nt]);
            if (row + 8 < M) *(float2*)&out[(size_t)(row + 8) * ostride + col] = make_float2(d2[mt][nt], d3[mt][nt]);
        }
    }
}

// ---- fused edge kernel: tile = 32 edges -> 64 edge-dir rows ----
constexpr int EST = 264;
constexpr int SM_EDGE = 64 * EST * 4;   // 67584 B

__global__ void __launch_bounds__(256, 3)
edge_fused(const float* __restrict__ AB, const float* __restrict__ ef,
           const float* __restrict__ fC, const float* __restrict__ fE2,
           const int* __restrict__ src, const int* __restrict__ dst,
           float* __restrict__ red, int E) {
    extern __shared__ float hs[];   // 64 * 264
    __shared__ int ss[64], dds[64];

    const int tid = threadIdx.x;
    const int t = blockIdx.x;

    if (tid < 64) {
        int er = tid >> 1;
        bool rev = tid & 1;
        int e = t * 32 + er;
        int sv = -1, dv = -1;
        if (e < E) { sv = src[e]; dv = dst[e]; }
        ss[tid]  = rev ? dv : sv;
        dds[tid] = rev ? sv : dv;
    }
    __syncthreads();

    const int w = tid >> 5, lane = tid & 31;
    const int fg = lane >> 2, fc = lane & 3;

    // ef byte offsets for this thread's 8 fragment rows (row -> edge row>>1)
    int eo[8];
#pragma unroll
    for (int j = 0; j < 8; j++) {
        int row = fg + j * 8;
        int e = t * 32 + (row >> 1);
        if (e >= E) e = 0;
        eo[j] = e * 64;
    }

    // ---- phase 1: C mma (K=64) + gather-add + leaky + rna -> hs ----
#pragma unroll
    for (int ch = 0; ch < 2; ch++) {           // N=256 per-warp NT=4, chunks of 2
        float d0[4][2], d1[4][2], d2[4][2], d3[4][2];
#pragma unroll
        for (int mt = 0; mt < 4; mt++)
#pragma unroll
            for (int nt = 0; nt < 2; nt++) { d0[mt][nt] = d1[mt][nt] = d2[mt][nt] = d3[mt][nt] = 0.f; }

#pragma unroll
        for (int kt = 0; kt < 8; kt++) {
            uint2 a[8];
#pragma unroll
            for (int j = 0; j < 8; j++)
                a[j] = __ldg((const uint2*)&ef[eo[j] + kt * 8 + 2 * fc]);
#pragma unroll
            for (int nt = 0; nt < 2; nt++) {
                int ntg = w * 4 + ch * 2 + nt;
                uint2 bv = __ldg((const uint2*)&fC[(size_t)(ntg * 8 + kt) * 64 + lane * 2]);
#pragma unroll
                for (int mt = 0; mt < 4; mt++)
                    MMA_TF32(d0[mt][nt], d1[mt][nt], d2[mt][nt], d3[mt][nt],
                             a[2 * mt], a[2 * mt + 1], bv);
            }
        }

#pragma unroll
        for (int mt = 0; mt < 4; mt++) {
#pragma unroll
            for (int nt = 0; nt < 2; nt++) {
                int row = mt * 16 + fg;
                int col = w * 32 + (ch * 2 + nt) * 8 + 2 * fc;
                {
                    int s = ss[row], d = dds[row];
                    float2 h = make_float2(0.f, 0.f);
                    if (s >= 0) {
                        float2 av = *(const float2*)&AB[(size_t)s * 512 + col];
                        float2 bvv = *(const float2*)&AB[(size_t)d * 512 + 256 + col];
                        h.x = rna_tf32(lky(d0[mt][nt] + av.x + bvv.x));
                        h.y = rna_tf32(lky(d1[mt][nt] + av.y + bvv.y));
                    }
                    *(float2*)&hs[row * EST + col] = h;
                }
                {
                    int r8 = row + 8;
                    int s = ss[r8], d = dds[r8];
                    float2 h = make_float2(0.f, 0.f);
                    if (s >= 0) {
                        float2 av = *(const float2*)&AB[(size_t)s * 512 + col];
                        float2 bvv = *(const float2*)&AB[(size_t)d * 512 + 256 + col];
                        h.x = rna_tf32(lky(d2[mt][nt] + av.x + bvv.x));
                        h.y = rna_tf32(lky(d3[mt][nt] + av.y + bvv.y));
                    }
                    *(float2*)&hs[r8 * EST + col] = h;
                }
            }
        }
    }
    __syncthreads();

    // ---- phase 2: msg = h @ We2 (K=256, N=128; per-warp NT=2) ----
    float e0[4][2], e1[4][2], e2[4][2], e3[4][2];
#pragma unroll
    for (int mt = 0; mt < 4; mt++)
#pragma unroll
        for (int nt = 0; nt < 2; nt++) { e0[mt][nt] = e1[mt][nt] = e2[mt][nt] = e3[mt][nt] = 0.f; }

    for (int kt = 0; kt < 32; kt++) {
        uint2 a[8];
#pragma unroll
        for (int j = 0; j < 8; j++)
            a[j] = *(const uint2*)&hs[(fg + j * 8) * EST + kt * 8 + 2 * fc];
#pragma unroll
        for (int nt = 0; nt < 2; nt++) {
            uint2 bv = __ldg((const uint2*)&fE2[(size_t)((w * 2 + nt) * 32 + kt) * 64 + lane * 2]);
#pragma unroll
            for (int mt = 0; mt < 4; mt++)
                MMA_TF32(e0[mt][nt], e1[mt][nt], e2[mt][nt], e3[mt][nt],
                         a[2 * mt], a[2 * mt + 1], bv);
        }
    }

    // ---- scatter-add (v4 via lane pairing) ----
#pragma unroll
    for (int mt = 0; mt < 4; mt++) {
        int rowA = mt * 16 + fg;
        int dA = dds[rowA];
        int dB = dds[rowA + 8];
#pragma unroll
        for (int nt = 0; nt < 2; nt++) {
            float s0 = __shfl_down_sync(0xffffffffu, e0[mt][nt], 1);
            float s1 = __shfl_down_sync(0xffffffffu, e1[mt][nt], 1);
            float s2 = __shfl_down_sync(0xffffffffu, e2[mt][nt], 1);
            float s3 = __shfl_down_sync(0xffffffffu, e3[mt][nt], 1);
            if ((fc & 1) == 0) {
                int col = w * 16 + nt * 8 + 2 * fc;   // fc even -> 4-aligned
                if (dA >= 0) red_add_v4(&red[(size_t)dA * 128 + col], e0[mt][nt], e1[mt][nt], s0, s1);
                if (dB >= 0) red_add_v4(&red[(size_t)dB * 128 + col], e2[mt][nt], e3[mt][nt], s2, s3);
            }
        }
    }
}

// ---- fused node MLP: hn = leaky([nf|red] @ Wn1); out = hn @ Wn2 ----
__global__ void __launch_bounds__(256, 2)
node_fused(const float* __restrict__ nf, const float* __restrict__ red,
           const float* __restrict__ fN1, const float* __restrict__ fN2,
           float* __restrict__ out, int M) {
    extern __shared__ float xs[];   // 64 * 264
    const int tid = threadIdx.x;
    const int row0 = blockIdx.x * 64;

    for (int idx = tid; idx < 64 * 64; idx += 256) {
        int r = idx >> 6, k4 = idx & 63;
        int row = row0 + r;
        float4 v = make_float4(0.f, 0.f, 0.f, 0.f);
        if (row < M)
            v = (k4 < 32) ? ((const float4*)nf)[(size_t)row * 32 + k4]
                          : ((const float4*)red)[(size_t)row * 32 + (k4 - 32)];
        v.x = rna_tf32(v.x); v.y = rna_tf32(v.y);
        v.z = rna_tf32(v.z); v.w = rna_tf32(v.w);
        *(float4*)&xs[r * EST + k4 * 4] = v;
    }
    __syncthreads();

    const int w = tid >> 5, lane = tid & 31;
    const int fg = lane >> 2, fc = lane & 3;

    // stage 1: hn frags (N=256, per-warp NT=4)
    float h0[4][4], h1[4][4], h2[4][4], h3[4][4];
#pragma unroll
    for (int mt = 0; mt < 4; mt++)
#pragma unroll
        for (int nt = 0; nt < 4; nt++) { h0[mt][nt] = h1[mt][nt] = h2[mt][nt] = h3[mt][nt] = 0.f; }

    for (int kt = 0; kt < 32; kt++) {
        uint2 a[8];
#pragma unroll
        for (int j = 0; j < 8; j++)
            a[j] = *(const uint2*)&xs[(fg + j * 8) * EST + kt * 8 + 2 * fc];
#pragma unroll
        for (int nt = 0; nt < 4; nt++) {
            uint2 bv = __ldg((const uint2*)&fN1[(size_t)((w * 4 + nt) * 32 + kt) * 64 + lane * 2]);
#pragma unroll
            for (int mt = 0; mt < 4; mt++)
                MMA_TF32(h0[mt][nt], h1[mt][nt], h2[mt][nt], h3[mt][nt],
                         a[2 * mt], a[2 * mt + 1], bv);
        }
    }
    __syncthreads();   // all xs reads complete before overwrite

#pragma unroll
    for (int mt = 0; mt < 4; mt++) {
#pragma unroll
        for (int nt = 0; nt < 4; nt++) {
            int row = mt * 16 + fg;
            int col = w * 32 + nt * 8 + 2 * fc;
            *(float2*)&xs[row * EST + col] =
                make_float2(rna_tf32(lky(h0[mt][nt])), rna_tf32(lky(h1[mt][nt])));
            *(float2*)&xs[(row + 8) * EST + col] =
                make_float2(rna_tf32(lky(h2[mt][nt])), rna_tf32(lky(h3[mt][nt])));
        }
    }
    __syncthreads();

    // stage 2: out = hn @ Wn2 (N=128, per-warp NT=2)
    float o0[4][2], o1[4][2], o2[4][2], o3[4][2];
#pragma unroll
    for (int mt = 0; mt < 4; mt++)
#pragma unroll
        for (int nt = 0; nt < 2; nt++) { o0[mt][nt] = o1[mt][nt] = o2[mt][nt] = o3[mt][nt] = 0.f; }

    for (int kt = 0; kt < 32; kt++) {
        uint2 a[8];
#pragma unroll
        for (int j = 0; j < 8; j++)
            a[j] = *(const uint2*)&xs[(fg + j * 8) * EST + kt * 8 + 2 * fc];
#pragma unroll
        for (int nt = 0; nt < 2; nt++) {
            uint2 bv = __ldg((const uint2*)&fN2[(size_t)((w * 2 + nt) * 32 + kt) * 64 + lane * 2]);
#pragma unroll
            for (int mt = 0; mt < 4; mt++)
                MMA_TF32(o0[mt][nt], o1[mt][nt], o2[mt][nt], o3[mt][nt],
                         a[2 * mt], a[2 * mt + 1], bv);
        }
    }

#pragma unroll
    for (int mt = 0; mt < 4; mt++) {
#pragma unroll
        for (int nt = 0; nt < 2; nt++) {
            int row = row0 + mt * 16 + fg;
            int col = w * 16 + nt * 8 + 2 * fc;
            if (row < M)     *(float2*)&out[(size_t)row * 128 + col]       = make_float2(o0[mt][nt], o1[mt][nt]);
            if (row + 8 < M) *(float2*)&out[(size_t)(row + 8) * 128 + col] = make_float2(o2[mt][nt], o3[mt][nt]);
        }
    }
}

extern "C" void kernel_launch(void* const* d_in, const int* in_sizes, int n_in,
                              void* d_out, int out_size) {
    const float* nf  = (const float*)d_in[0];
    const float* ef  = (const float*)d_in[1];
    const int*   src = (const int*)d_in[2];
    const int*   dst = (const int*)d_in[3];
    const float* We1 = (const float*)d_in[4];   // (320, 256)
    const float* We2 = (const float*)d_in[5];   // (256, 128)
    const float* Wn1 = (const float*)d_in[6];   // (256, 256)
    const float* Wn2 = (const float*)d_in[7];   // (256, 128)

    const int N = in_sizes[0] / 128;
    const int E = in_sizes[2];

    float *AB, *red, *fA, *fB, *fC, *fN1, *fN2, *fE2;
    cudaGetSymbolAddress((void**)&AB, g_AB);
    cudaGetSymbolAddress((void**)&red, g_red);
    cudaGetSymbolAddress((void**)&fA, g_fA);
    cudaGetSymbolAddress((void**)&fB, g_fB);
    cudaGetSymbolAddress((void**)&fC, g_fC);
    cudaGetSymbolAddress((void**)&fN1, g_fN1);
    cudaGetSymbolAddress((void**)&fN2, g_fN2);
    cudaGetSymbolAddress((void**)&fE2, g_fE2);

    cudaFuncSetAttribute((const void*)edge_fused,
                         cudaFuncAttributeMaxDynamicSharedMemorySize, SM_EDGE);
    cudaFuncSetAttribute((const void*)node_fused,
                         cudaFuncAttributeMaxDynamicSharedMemorySize, 64 * EST * 4);

    // one-time weight shuffles
    setup_frag<128, 256><<<(128 * 256 + 255) / 256, 256>>>(We1, fA);
    setup_frag<128, 256><<<(128 * 256 + 255) / 256, 256>>>(We1 + 128 * 256, fB);
    setup_frag<64, 256><<<(64 * 256 + 255) / 256, 256>>>(We1 + 256 * 256, fC);
    setup_frag<256, 256><<<(256 * 256 + 255) / 256, 256>>>(Wn1, fN1);
    setup_frag<256, 128><<<(256 * 128 + 255) / 256, 256>>>(Wn2, fN2);
    setup_frag<256, 128><<<(256 * 128 + 255) / 256, 256>>>(We2, fE2);

    // zero segment-sum accumulator
    int n4 = N * 128 / 4;
    zero_kernel<<<(n4 + 255) / 256, 256>>>((float4*)red, n4);

    // A|B halves: nf @ We1 halves -> g_AB (row stride 512)
    mma_gemm<128, 256><<<(N + 63) / 64, 256, 64 * 136 * 4>>>(nf, fA, AB, N, 512);
    mma_gemm<128, 256><<<(N + 63) / 64, 256, 64 * 136 * 4>>>(nf, fB, AB + 256, N, 512);

    // fused edge: C mma + gather + msg mma + scatter
    edge_fused<<<(E + 31) / 32, 256, SM_EDGE>>>(AB, ef, fC, fE2, src, dst, red, E);

    // fused node MLP
    node_fused<<<(N + 63) / 64, 256, 64 * EST * 4>>>(nf, red, fN1, fN2, (float*)d_out, N);
}

// round 7
// speedup vs baseline: 1.9142x; 1.0790x over previous
#include <cuda_runtime.h>
#include <cstdint>

// GNN layer, all GEMMs on tf32 mma.sync m16n8k8:
//   A|B = nf @ [We1_rows0:128 | We1_rows128:256]   (per node, precomputed)
//   edge (fused): Cfrag = ef @ We1_ef (mma, M=32, computed ONCE per edge);
//                 expand: h_fwd/h_rev = rna(leaky(C + A[s]+B[d] / A[d]+B[s])) -> smem (64 rows);
//                 msg = h @ We2 (mma, M=64); red.global.add.v4 into red[dst]
//   node (fused): hn = leaky([nf|red] @ Wn1) -> smem; out = hn @ Wn2
// Weight fragments pre-shuffled (coalesced LDG.64 B-frags):
//   Wf[((ntg*(K/8)+kt)*64 + lane*2 + j)] = rna(W[(kt*8+2*(lane&3)+j)*N + ntg*8 + (lane>>2)])

constexpr int NN_MAX = 100000;
constexpr int NE_MAX = 500000;
constexpr float NEG = 0.01f;

__device__ __align__(128) float g_AB[(size_t)NN_MAX * 512];
__device__ __align__(128) float g_red[(size_t)NN_MAX * 128];
__device__ __align__(128) float g_fA[128 * 256];
__device__ __align__(128) float g_fB[128 * 256];
__device__ __align__(128) float g_fC[64 * 256];
__device__ __align__(128) float g_fN1[256 * 256];
__device__ __align__(128) float g_fN2[256 * 128];
__device__ __align__(128) float g_fE2[256 * 128];

__device__ __forceinline__ float lky(float x) { return x >= 0.0f ? x : NEG * x; }

__device__ __forceinline__ float rna_tf32(float x) {
    float r; asm("cvt.rna.tf32.f32 %0, %1;" : "=f"(r) : "f"(x)); return r;
}

__device__ __forceinline__ void red_add_v4(float* addr, float a, float b, float c, float d) {
    asm volatile("red.global.add.v4.f32 [%0], {%1,%2,%3,%4};"
                 :: "l"(addr), "f"(a), "f"(b), "f"(c), "f"(d) : "memory");
}

#define MMA_TF32(D0, D1, D2, D3, AV, AV8, BV)                                   \
    asm volatile("mma.sync.aligned.m16n8k8.row.col.f32.tf32.tf32.f32 "          \
                 "{%0,%1,%2,%3}, {%4,%5,%6,%7}, {%8,%9}, {%0,%1,%2,%3};"        \
                 : "+f"(D0), "+f"(D1), "+f"(D2), "+f"(D3)                       \
                 : "r"((AV).x), "r"((AV8).x), "r"((AV).y), "r"((AV8).y),        \
                   "r"((BV).x), "r"((BV).y))

// ---- merged one-time setup: zero red + all weight fragment shuffles ----
template <int K, int N>
__device__ __forceinline__ void do_frag(int fi, const float* __restrict__ W,
                                        float* __restrict__ Wf) {
    if (fi >= K * N) return;
    int j = fi & 1;
    int lane = (fi >> 1) & 31;
    int kt = (fi >> 6) % (K / 8);
    int ntg = fi / (64 * (K / 8));
    int fc = lane & 3, fg = lane >> 2;
    Wf[fi] = rna_tf32(W[(kt * 8 + 2 * fc + j) * N + ntg * 8 + fg]);
}

__global__ void setup_all(const float* __restrict__ We1, const float* __restrict__ We2,
                          const float* __restrict__ Wn1, const float* __restrict__ Wn2,
                          float4* __restrict__ red4, int n4,
                          float* fA, float* fB, float* fC,
                          float* fN1, float* fN2, float* fE2) {
    int tid = blockIdx.x * 256 + threadIdx.x;
    if (tid < n4) red4[tid] = make_float4(0.f, 0.f, 0.f, 0.f);
    do_frag<128, 256>(tid, We1, fA);
    do_frag<128, 256>(tid, We1 + 128 * 256, fB);
    do_frag<64, 256>(tid, We1 + 256 * 256, fC);
    do_frag<256, 256>(tid, Wn1, fN1);
    do_frag<256, 128>(tid, Wn2, fN2);
    do_frag<256, 128>(tid, We2, fE2);
}

// ---- generic tf32 mma GEMM, 1(M)x8(N) warp grid, tile M=64 ----
template <int K, int N>
__global__ void __launch_bounds__(256, 2)
mma_gemm(const float* __restrict__ X1, const float* __restrict__ Wf,
         float* __restrict__ out, int M, int ostride) {
    constexpr int ST = K + 8;
    constexpr int KT = K / 8;
    constexpr int NT = N / 64;
    constexpr int K4 = K / 4;
    extern __shared__ float xs[];

    const int tid = threadIdx.x;
    const int row0 = blockIdx.x * 64;

    for (int idx = tid; idx < 64 * K4; idx += 256) {
        int r = idx / K4, k4 = idx % K4;
        int row = row0 + r;
        float4 v = make_float4(0.f, 0.f, 0.f, 0.f);
        if (row < M) v = ((const float4*)X1)[(size_t)row * K4 + k4];
        v.x = rna_tf32(v.x); v.y = rna_tf32(v.y);
        v.z = rna_tf32(v.z); v.w = rna_tf32(v.w);
        *(float4*)&xs[r * ST + k4 * 4] = v;
    }
    __syncthreads();

    const int w = tid >> 5, lane = tid & 31;
    const int fg = lane >> 2, fc = lane & 3;

    float d0[4][NT], d1[4][NT], d2[4][NT], d3[4][NT];
#pragma unroll
    for (int mt = 0; mt < 4; mt++)
#pragma unroll
        for (int nt = 0; nt < NT; nt++) { d0[mt][nt] = d1[mt][nt] = d2[mt][nt] = d3[mt][nt] = 0.f; }

    for (int kt = 0; kt < KT; kt++) {
        uint2 a[8];
#pragma unroll
        for (int j = 0; j < 8; j++)
            a[j] = *(const uint2*)&xs[(fg + j * 8) * ST + kt * 8 + 2 * fc];
#pragma unroll
        for (int nt = 0; nt < NT; nt++) {
            uint2 bv = __ldg((const uint2*)&Wf[(size_t)((w * NT + nt) * KT + kt) * 64 + lane * 2]);
#pragma unroll
            for (int mt = 0; mt < 4; mt++)
                MMA_TF32(d0[mt][nt], d1[mt][nt], d2[mt][nt], d3[mt][nt],
                         a[2 * mt], a[2 * mt + 1], bv);
        }
    }

#pragma unroll
    for (int mt = 0; mt < 4; mt++) {
#pragma unroll
        for (int nt = 0; nt < NT; nt++) {
            int row = row0 + mt * 16 + fg;
            int col = w * (NT * 8) + nt * 8 + 2 * fc;
            if (row < M)     *(float2*)&out[(size_t)row * ostride + col]       = make_float2(d0[mt][nt], d1[mt][nt]);
            if (row + 8 < M) *(float2*)&out[(size_t)(row + 8) * ostride + col] = make_float2(d2[mt][nt], d3[mt][nt]);
        }
    }
}

// ---- fused edge kernel: tile = 32 edges -> 64 edge-dir rows ----
constexpr int EST = 264;
constexpr int SM_EDGE = 64 * EST * 4;   // 67584 B

__global__ void __launch_bounds__(256, 3)
edge_fused(const float* __restrict__ AB, const float* __restrict__ ef,
           const float* __restrict__ fC, const float* __restrict__ fE2,
           const int* __restrict__ src, const int* __restrict__ dst,
           float* __restrict__ red, int E) {
    extern __shared__ float hs[];   // 64 * 264
    __shared__ int ss[64], dds[64];

    const int tid = threadIdx.x;
    const int t = blockIdx.x;

    if (tid < 64) {
        int er = tid >> 1;
        bool rev = tid & 1;
        int e = t * 32 + er;
        int sv = -1, dv = -1;
        if (e < E) { sv = src[e]; dv = dst[e]; }
        ss[tid]  = rev ? dv : sv;
        dds[tid] = rev ? sv : dv;
    }
    __syncthreads();

    const int w = tid >> 5, lane = tid & 31;
    const int fg = lane >> 2, fc = lane & 3;

    // ef element offsets for this thread's 4 fragment edge-rows (M=32 C tile)
    int eo[4];
#pragma unroll
    for (int j = 0; j < 4; j++) {
        int e = t * 32 + fg + j * 8;
        if (e >= E) e = 0;
        eo[j] = e * 64;
    }

    // ---- phase 1: C mma (M=32, K=64) once per edge, expand to both dirs ----
#pragma unroll
    for (int ch = 0; ch < 2; ch++) {           // per-warp NT=4, chunks of 2
        float d0[2][2], d1[2][2], d2[2][2], d3[2][2];
#pragma unroll
        for (int mt = 0; mt < 2; mt++)
#pragma unroll
            for (int nt = 0; nt < 2; nt++) { d0[mt][nt] = d1[mt][nt] = d2[mt][nt] = d3[mt][nt] = 0.f; }

#pragma unroll
        for (int kt = 0; kt < 8; kt++) {
            uint2 a[4];
#pragma unroll
            for (int j = 0; j < 4; j++)
                a[j] = __ldg((const uint2*)&ef[eo[j] + kt * 8 + 2 * fc]);
#pragma unroll
            for (int nt = 0; nt < 2; nt++) {
                int ntg = w * 4 + ch * 2 + nt;
                uint2 bv = __ldg((const uint2*)&fC[(size_t)(ntg * 8 + kt) * 64 + lane * 2]);
#pragma unroll
                for (int mt = 0; mt < 2; mt++)
                    MMA_TF32(d0[mt][nt], d1[mt][nt], d2[mt][nt], d3[mt][nt],
                             a[2 * mt], a[2 * mt + 1], bv);
            }
        }

        // expand each C element into fwd + rev h rows
#pragma unroll
        for (int mt = 0; mt < 2; mt++) {
#pragma unroll
            for (int nt = 0; nt < 2; nt++) {
                int col = w * 32 + (ch * 2 + nt) * 8 + 2 * fc;
#pragma unroll
                for (int half = 0; half < 2; half++) {
                    int er = mt * 16 + fg + half * 8;          // edge row 0..31
                    float cx = half ? d2[mt][nt] : d0[mt][nt];
                    float cy = half ? d3[mt][nt] : d1[mt][nt];
#pragma unroll
                    for (int dir = 0; dir < 2; dir++) {
                        int hr = 2 * er + dir;
                        int s = ss[hr], d = dds[hr];
                        float2 h = make_float2(0.f, 0.f);
                        if (s >= 0) {
                            float2 av = *(const float2*)&AB[(size_t)s * 512 + col];
                            float2 bv = *(const float2*)&AB[(size_t)d * 512 + 256 + col];
                            h.x = rna_tf32(lky(cx + av.x + bv.x));
                            h.y = rna_tf32(lky(cy + av.y + bv.y));
                        }
                        *(float2*)&hs[hr * EST + col] = h;
                    }
                }
            }
        }
    }
    __syncthreads();

    // ---- phase 2: msg = h @ We2 (M=64, K=256, N=128; per-warp NT=2) ----
    float e0[4][2], e1[4][2], e2[4][2], e3[4][2];
#pragma unroll
    for (int mt = 0; mt < 4; mt++)
#pragma unroll
        for (int nt = 0; nt < 2; nt++) { e0[mt][nt] = e1[mt][nt] = e2[mt][nt] = e3[mt][nt] = 0.f; }

    for (int kt = 0; kt < 32; kt++) {
        uint2 a[8];
#pragma unroll
        for (int j = 0; j < 8; j++)
            a[j] = *(const uint2*)&hs[(fg + j * 8) * EST + kt * 8 + 2 * fc];
#pragma unroll
        for (int nt = 0; nt < 2; nt++) {
            uint2 bv = __ldg((const uint2*)&fE2[(size_t)((w * 2 + nt) * 32 + kt) * 64 + lane * 2]);
#pragma unroll
            for (int mt = 0; mt < 4; mt++)
                MMA_TF32(e0[mt][nt], e1[mt][nt], e2[mt][nt], e3[mt][nt],
                         a[2 * mt], a[2 * mt + 1], bv);
        }
    }

    // ---- scatter-add (v4 via lane pairing) ----
#pragma unroll
    for (int mt = 0; mt < 4; mt++) {
        int rowA = mt * 16 + fg;
        int dA = dds[rowA];
        int dB = dds[rowA + 8];
#pragma unroll
        for (int nt = 0; nt < 2; nt++) {
            float s0 = __shfl_down_sync(0xffffffffu, e0[mt][nt], 1);
            float s1 = __shfl_down_sync(0xffffffffu, e1[mt][nt], 1);
            float s2 = __shfl_down_sync(0xffffffffu, e2[mt][nt], 1);
            float s3 = __shfl_down_sync(0xffffffffu, e3[mt][nt], 1);
            if ((fc & 1) == 0) {
                int col = w * 16 + nt * 8 + 2 * fc;
                if (dA >= 0) red_add_v4(&red[(size_t)dA * 128 + col], e0[mt][nt], e1[mt][nt], s0, s1);
                if (dB >= 0) red_add_v4(&red[(size_t)dB * 128 + col], e2[mt][nt], e3[mt][nt], s2, s3);
            }
        }
    }
}

// ---- fused node MLP: hn = leaky([nf|red] @ Wn1); out = hn @ Wn2 ----
__global__ void __launch_bounds__(256, 2)
node_fused(const float* __restrict__ nf, const float* __restrict__ red,
           const float* __restrict__ fN1, const float* __restrict__ fN2,
           float* __restrict__ out, int M) {
    extern __shared__ float xs[];   // 64 * 264
    const int tid = threadIdx.x;
    const int row0 = blockIdx.x * 64;

    for (int idx = tid; idx < 64 * 64; idx += 256) {
        int r = idx >> 6, k4 = idx & 63;
        int row = row0 + r;
        float4 v = make_float4(0.f, 0.f, 0.f, 0.f);
        if (row < M)
            v = (k4 < 32) ? ((const float4*)nf)[(size_t)row * 32 + k4]
                          : ((const float4*)red)[(size_t)row * 32 + (k4 - 32)];
        v.x = rna_tf32(v.x); v.y = rna_tf32(v.y);
        v.z = rna_tf32(v.z); v.w = rna_tf32(v.w);
        *(float4*)&xs[r * EST + k4 * 4] = v;
    }
    __syncthreads();

    const int w = tid >> 5, lane = tid & 31;
    const int fg = lane >> 2, fc = lane & 3;

    float h0[4][4], h1[4][4], h2[4][4], h3[4][4];
#pragma unroll
    for (int mt = 0; mt < 4; mt++)
#pragma unroll
        for (int nt = 0; nt < 4; nt++) { h0[mt][nt] = h1[mt][nt] = h2[mt][nt] = h3[mt][nt] = 0.f; }

    for (int kt = 0; kt < 32; kt++) {
        uint2 a[8];
#pragma unroll
        for (int j = 0; j < 8; j++)
            a[j] = *(const uint2*)&xs[(fg + j * 8) * EST + kt * 8 + 2 * fc];
#pragma unroll
        for (int nt = 0; nt < 4; nt++) {
            uint2 bv = __ldg((const uint2*)&fN1[(size_t)((w * 4 + nt) * 32 + kt) * 64 + lane * 2]);
#pragma unroll
            for (int mt = 0; mt < 4; mt++)
                MMA_TF32(h0[mt][nt], h1[mt][nt], h2[mt][nt], h3[mt][nt],
                         a[2 * mt], a[2 * mt + 1], bv);
        }
    }
    __syncthreads();

#pragma unroll
    for (int mt = 0; mt < 4; mt++) {
#pragma unroll
        for (int nt = 0; nt < 4; nt++) {
            int row = mt * 16 + fg;
            int col = w * 32 + nt * 8 + 2 * fc;
            *(float2*)&xs[row * EST + col] =
                make_float2(rna_tf32(lky(h0[mt][nt])), rna_tf32(lky(h1[mt][nt])));
            *(float2*)&xs[(row + 8) * EST + col] =
                make_float2(rna_tf32(lky(h2[mt][nt])), rna_tf32(lky(h3[mt][nt])));
        }
    }
    __syncthreads();

    float o0[4][2], o1[4][2], o2[4][2], o3[4][2];
#pragma unroll
    for (int mt = 0; mt < 4; mt++)
#pragma unroll
        for (int nt = 0; nt < 2; nt++) { o0[mt][nt] = o1[mt][nt] = o2[mt][nt] = o3[mt][nt] = 0.f; }

    for (int kt = 0; kt < 32; kt++) {
        uint2 a[8];
#pragma unroll
        for (int j = 0; j < 8; j++)
            a[j] = *(const uint2*)&xs[(fg + j * 8) * EST + kt * 8 + 2 * fc];
#pragma unroll
        for (int nt = 0; nt < 2; nt++) {
            uint2 bv = __ldg((const uint2*)&fN2[(size_t)((w * 2 + nt) * 32 + kt) * 64 + lane * 2]);
#pragma unroll
            for (int mt = 0; mt < 4; mt++)
                MMA_TF32(o0[mt][nt], o1[mt][nt], o2[mt][nt], o3[mt][nt],
                         a[2 * mt], a[2 * mt + 1], bv);
        }
    }

#pragma unroll
    for (int mt = 0; mt < 4; mt++) {
#pragma unroll
        for (int nt = 0; nt < 2; nt++) {
            int row = row0 + mt * 16 + fg;
            int col = w * 16 + nt * 8 + 2 * fc;
            if (row < M)     *(float2*)&out[(size_t)row * 128 + col]       = make_float2(o0[mt][nt], o1[mt][nt]);
            if (row + 8 < M) *(float2*)&out[(size_t)(row + 8) * 128 + col] = make_float2(o2[mt][nt], o3[mt][nt]);
        }
    }
}

extern "C" void kernel_launch(void* const* d_in, const int* in_sizes, int n_in,
                              void* d_out, int out_size) {
    const float* nf  = (const float*)d_in[0];
    const float* ef  = (const float*)d_in[1];
    const int*   src = (const int*)d_in[2];
    const int*   dst = (const int*)d_in[3];
    const float* We1 = (const float*)d_in[4];   // (320, 256)
    const float* We2 = (const float*)d_in[5];   // (256, 128)
    const float* Wn1 = (const float*)d_in[6];   // (256, 256)
    const float* Wn2 = (const float*)d_in[7];   // (256, 128)

    const int N = in_sizes[0] / 128;
    const int E = in_sizes[2];

    float *AB, *red, *fA, *fB, *fC, *fN1, *fN2, *fE2;
    cudaGetSymbolAddress((void**)&AB, g_AB);
    cudaGetSymbolAddress((void**)&red, g_red);
    cudaGetSymbolAddress((void**)&fA, g_fA);
    cudaGetSymbolAddress((void**)&fB, g_fB);
    cudaGetSymbolAddress((void**)&fC, g_fC);
    cudaGetSymbolAddress((void**)&fN1, g_fN1);
    cudaGetSymbolAddress((void**)&fN2, g_fN2);
    cudaGetSymbolAddress((void**)&fE2, g_fE2);

    cudaFuncSetAttribute((const void*)edge_fused,
                         cudaFuncAttributeMaxDynamicSharedMemorySize, SM_EDGE);
    cudaFuncSetAttribute((const void*)node_fused,
                         cudaFuncAttributeMaxDynamicSharedMemorySize, 64 * EST * 4);

    // (0) merged one-time setup: zero red + all weight fragment shuffles
    int n4 = N * 128 / 4;
    setup_all<<<(n4 + 255) / 256, 256>>>(We1, We2, Wn1, Wn2,
                                         (float4*)red, n4, fA, fB, fC, fN1, fN2, fE2);

    // (1,2) A|B halves: nf @ We1 halves -> g_AB (row stride 512)
    mma_gemm<128, 256><<<(N + 63) / 64, 256, 64 * 136 * 4>>>(nf, fA, AB, N, 512);
    mma_gemm<128, 256><<<(N + 63) / 64, 256, 64 * 136 * 4>>>(nf, fB, AB + 256, N, 512);

    // (3) fused edge: C mma (deduped) + expand-gather + msg mma + scatter
    edge_fused<<<(E + 31) / 32, 256, SM_EDGE>>>(AB, ef, fC, fE2, src, dst, red, E);

    // (4) fused node MLP
    node_fused<<<(N + 63) / 64, 256, 64 * EST * 4>>>(nf, red, fN1, fN2, (float*)d_out, N);
}